// round 17
// baseline (speedup 1.0000x reference)
#include <cuda_runtime.h>
#include <cuda_bf16.h>
#include <cstdint>

#define B_   64
#define T_   512
#define I_   512
#define H_   512
#define G4   2048
#define NCG  256
#define SEG  128                                         // timesteps per K2 launch

// ------------------------- device scratch ----------------------------------
__device__ uint4    g_WhFrag[64 * 4096];                // [jc][(kb*4+nf)*32+lane] (Wh rows I_+k)
__device__ uint4    g_WxF[64 * 4096];                   // [jc][(kb*4+nf)*32+lane] (Wx rows k)
__device__ float    g_bias[G4];
__device__ uint2    g_xP[(size_t)T_ * B_ * 256];        // [t][b][k2] {hi-pair, lo-pair} of x
__device__ uint2    g_hP[2][B_ * 256];                  // [buf][b][k2] {hi-pair, lo-pair}
__device__ float    g_cs[B_ * H_];                      // cell state between segments
__device__ int      g_count4[4];                        // per-batch-group barrier counters

// ------------------------- helpers -----------------------------------------
__device__ __forceinline__ void bsplit(float v, uint16_t& hi, uint16_t& lo) {
    __nv_bfloat16 h = __float2bfloat16_rn(v);
    float r = v - __bfloat162float(h);
    __nv_bfloat16 l = __float2bfloat16_rn(r);
    hi = __bfloat16_as_ushort(h);
    lo = __bfloat16_as_ushort(l);
}
__device__ __forceinline__ uint32_t bpack(uint16_t e0, uint16_t e1) {
    return (uint32_t)e0 | ((uint32_t)e1 << 16);
}

__device__ __forceinline__ float sigm(float x) { return 1.0f / (1.0f + __expf(-x)); }
__device__ __forceinline__ float tanh_acc(float x) {
    return 1.0f - 2.0f / (__expf(2.0f * x) + 1.0f);
}

__device__ __forceinline__ int ld_acq(const int* p) {
    int v;
    asm volatile("ld.acquire.gpu.global.b32 %0, [%1];" : "=r"(v) : "l"(p) : "memory");
    return v;
}
__device__ __forceinline__ void red_rel(int* p) {
    asm volatile("red.release.gpu.global.add.s32 [%0], %1;" :: "l"(p), "r"(1) : "memory");
}

__device__ __forceinline__ void mma_bf16(float (&d)[4], const uint32_t (&a)[4],
                                         uint32_t b0, uint32_t b1) {
    asm volatile(
        "mma.sync.aligned.m16n8k16.row.col.f32.bf16.bf16.f32 "
        "{%0,%1,%2,%3}, {%4,%5,%6,%7}, {%8,%9}, {%0,%1,%2,%3};"
        : "+f"(d[0]), "+f"(d[1]), "+f"(d[2]), "+f"(d[3])
        : "r"(a[0]), "r"(a[1]), "r"(a[2]), "r"(a[3]), "r"(b0), "r"(b1));
}

__device__ __forceinline__ const float* wsel(int gate, const float* Wf, const float* Wi,
                                             const float* Wo, const float* Wc) {
    return gate == 0 ? Wf : gate == 1 ? Wi : gate == 2 ? Wo : Wc;
}

// ------------------------- K0: pack ----------------------------------------
// WhFrag: rows I_+k (recurrent part). WxF: rows k (input part). SAME index math.
__global__ void pack_kernel(const float* __restrict__ Wf, const float* __restrict__ Wi,
                            const float* __restrict__ Wo, const float* __restrict__ Wc,
                            const float* __restrict__ bf, const float* __restrict__ bi,
                            const float* __restrict__ bo, const float* __restrict__ bc) {
    int idx = blockIdx.x * blockDim.x + threadIdx.x;
    if (idx < 64 * 4096 * 2) {
        int which = idx >= 64 * 4096;                   // 0 = Wh, 1 = Wx
        int id = idx & (64 * 4096 - 1);
        int lane = id & 31, nf = (id >> 5) & 3, kb = (id >> 7) & 31, jc = id >> 12;
        int g = lane >> 2, tg = lane & 3;
        int k0 = kb * 16 + 2 * tg;
        int rowoff = which ? 0 : I_;                    // Wx: rows k; Wh: rows I_+k
        const float* W = wsel(nf, Wf, Wi, Wo, Wc);
        const size_t base = (size_t)(rowoff + k0) * H_ + jc * 8 + g;
        float v00 = W[base];
        float v01 = W[base + H_];
        float v10 = W[base + 8 * H_];
        float v11 = W[base + 9 * H_];
        uint16_t h00, l00, h01, l01, h10, l10, h11, l11;
        bsplit(v00, h00, l00); bsplit(v01, h01, l01);
        bsplit(v10, h10, l10); bsplit(v11, h11, l11);
        uint4 frag;
        frag.x = bpack(h00, h01);
        frag.y = bpack(h10, h11);
        frag.z = bpack(l00, l01);
        frag.w = bpack(l10, l11);
        if (which) g_WxF[id] = frag;
        else       g_WhFrag[id] = frag;
    }
    if (idx < G4) {
        int gate = idx >> 9, j = idx & 511;
        const float* b = gate == 0 ? bf : gate == 1 ? bi : gate == 2 ? bo : bc;
        g_bias[idx] = b[j];
    }
    if (idx < B_ * 256) g_hP[0][idx] = make_uint2(0u, 0u);   // h_0 = 0
    if (idx < B_ * H_) g_cs[idx] = 0.0f;
    if (idx < 4) g_count4[idx] = 0;
}

// ------------------------- K0b: pack x into hi/lo bf16 pairs ----------------
// g_xP[(t*64+b)*256 + k2] = {bpack(hi(x0),hi(x1)), bpack(lo(x0),lo(x1))},
// x0/x1 = x[b][t][2k2], [2k2+1].  Same pair convention as g_hP.
__global__ void xpack_kernel(const float* __restrict__ x) {
    int idx = blockIdx.x * blockDim.x + threadIdx.x;    // over T_*B_*256
    int t = idx >> 14;
    int rem = idx & 16383;
    int b = rem >> 8, k2 = rem & 255;
    const float* src = x + ((size_t)b * T_ + t) * I_ + 2 * k2;
    float v0 = src[0], v1 = src[1];
    uint16_t h0, l0, h1, l1;
    bsplit(v0, h0, l0);
    bsplit(v1, h1, l1);
    g_xP[idx] = make_uint2(bpack(h0, h1), bpack(l0, l1));
}

// ------------------------- K2: fused recurrence + xproj (3xBF16) ------------
// 256 CTAs x 128 thr, 2 CTAs/SM. CTA (mb, jc): batch rows [16mb,+16),
// hidden [8jc,+8). Per step: hGEMM(t) from smem Wh frags + direct-LDG h,
// AND xGEMM(t+1) from L2-streamed Wx frags + g_xP (fills latency bubbles).
// Partials for both go through sP; distributed epilogue (1 elem/thread).
#define SMEM2 (65536 + 16384)

__global__ void __launch_bounds__(128, 2) lstm_kernel(float* __restrict__ out, int t0) {
    extern __shared__ char smemraw[];
    uint4* sWf = (uint4*)smemraw;                 // [32 kb][4 nf][32 lane] Wh frags
    float* sPh = (float*)(smemraw + 65536);       // [4 w][4 nf][16 b][8 j] h partials
    float* sPx = sPh + 2048;                      // same layout, x partials

    const int tid = threadIdx.x;
    const int bxid = blockIdx.x;
    const int mb = bxid >> 6, jc = bxid & 63;
    const int lane = tid & 31, w = tid >> 5;
    const int g = lane >> 2, tg = lane & 3;
    const int bloc = tid >> 3, jloc = tid & 7;    // epilogue element (b, j)
    const int bglob = mb * 16 + bloc;
    const int jglob = jc * 8 + jloc;
    const int rowbase = mb * 16;

    {   // Wh fragments -> smem (contract from pack)
        const uint4* src = g_WhFrag + (size_t)jc * 4096;
        for (int i = tid; i < 4096; i += 128) sWf[i] = src[i];
    }
    const uint4* wxf = g_WxF + (size_t)jc * 4096;     // Wx frags stay in L2

    float cs = g_cs[(size_t)bglob * H_ + jglob];
    float bias_r[4];
#pragma unroll
    for (int nf = 0; nf < 4; nf++) bias_r[nf] = g_bias[nf * 512 + jglob];
    __syncthreads();

    float xp[4];
    {   // ---- cold start: xproj partial for t0 ----
        const uint2* xpp = g_xP + (size_t)t0 * (B_ * 256);
        float xa[4][4] = {}, xb[4][4] = {};
#pragma unroll
        for (int kbi = 0; kbi < 8; kbi++) {
            const int kb = w * 8 + kbi;
            const int wa = kb * 8 + tg;
            uint2 v0 = __ldg(&xpp[(rowbase + g) * 256 + wa]);
            uint2 v1 = __ldg(&xpp[(rowbase + g + 8) * 256 + wa]);
            uint2 v2 = __ldg(&xpp[(rowbase + g) * 256 + wa + 4]);
            uint2 v3 = __ldg(&xpp[(rowbase + g + 8) * 256 + wa + 4]);
            uint32_t ahi[4] = {v0.x, v1.x, v2.x, v3.x};
            uint32_t alo[4] = {v0.y, v1.y, v2.y, v3.y};
#pragma unroll
            for (int nf = 0; nf < 4; nf++) {
                uint4 wf = __ldg(&wxf[(kb * 4 + nf) * 32 + lane]);
                mma_bf16(xa[nf], ahi, wf.x, wf.y);
                mma_bf16(xb[nf], ahi, wf.z, wf.w);
                mma_bf16(xb[nf], alo, wf.x, wf.y);
            }
        }
#pragma unroll
        for (int nf = 0; nf < 4; nf++)
#pragma unroll
            for (int q = 0; q < 4; q++) {
                int bq = g + 8 * (q >> 1), jq = tg * 2 + (q & 1);
                sPx[((w * 4 + nf) * 16 + bq) * 8 + jq] = xa[nf][q] + xb[nf][q];
            }
        __syncthreads();
#pragma unroll
        for (int nf = 0; nf < 4; nf++) {
            float s = bias_r[nf];
#pragma unroll
            for (int ww = 0; ww < 4; ww++)
                s += sPx[((ww * 4 + nf) * 16 + bloc) * 8 + jloc];
            xp[nf] = s;
        }
        __syncthreads();
    }

    for (int t = t0; t < t0 + SEG; t++) {
        const bool dox = (t + 1 < t0 + SEG);

        // ---- hGEMM(t): A-frags direct from g_hP, B from smem ----
        const uint2* hp = g_hP[t & 1];
        float acc1[4][4] = {}, acc2[4][4] = {}, acc3[4][4] = {};
#pragma unroll
        for (int kbi = 0; kbi < 8; kbi++) {
            const int kb = w * 8 + kbi;
            const int wa = kb * 8 + tg;
            uint2 v0 = __ldcg(&hp[(rowbase + g) * 256 + wa]);
            uint2 v1 = __ldcg(&hp[(rowbase + g + 8) * 256 + wa]);
            uint2 v2 = __ldcg(&hp[(rowbase + g) * 256 + wa + 4]);
            uint2 v3 = __ldcg(&hp[(rowbase + g + 8) * 256 + wa + 4]);
            uint32_t ahi[4] = {v0.x, v1.x, v2.x, v3.x};
            uint32_t alo[4] = {v0.y, v1.y, v2.y, v3.y};
            const uint4* wfb = sWf + (kb * 4) * 32 + lane;
#pragma unroll
            for (int nf = 0; nf < 4; nf++) {
                uint4 wf = wfb[nf * 32];
                mma_bf16(acc1[nf], ahi, wf.x, wf.y);
                mma_bf16(acc2[nf], ahi, wf.z, wf.w);
                mma_bf16(acc3[nf], alo, wf.x, wf.y);
            }
        }

        // ---- xGEMM(t+1): B-frags streamed from L2, A from g_xP ----
        float xa[4][4] = {}, xb[4][4] = {};
        if (dox) {
            const uint2* xpp = g_xP + (size_t)(t + 1) * (B_ * 256);
#pragma unroll
            for (int kbi = 0; kbi < 8; kbi++) {
                const int kb = w * 8 + kbi;
                const int wa = kb * 8 + tg;
                uint2 v0 = __ldg(&xpp[(rowbase + g) * 256 + wa]);
                uint2 v1 = __ldg(&xpp[(rowbase + g + 8) * 256 + wa]);
                uint2 v2 = __ldg(&xpp[(rowbase + g) * 256 + wa + 4]);
                uint2 v3 = __ldg(&xpp[(rowbase + g + 8) * 256 + wa + 4]);
                uint32_t ahi[4] = {v0.x, v1.x, v2.x, v3.x};
                uint32_t alo[4] = {v0.y, v1.y, v2.y, v3.y};
#pragma unroll
                for (int nf = 0; nf < 4; nf++) {
                    uint4 wf = __ldg(&wxf[(kb * 4 + nf) * 32 + lane]);
                    mma_bf16(xa[nf], ahi, wf.x, wf.y);
                    mma_bf16(xb[nf], ahi, wf.z, wf.w);
                    mma_bf16(xb[nf], alo, wf.x, wf.y);
                }
            }
        }

        // ---- publish partials ----
#pragma unroll
        for (int nf = 0; nf < 4; nf++)
#pragma unroll
            for (int q = 0; q < 4; q++) {
                int bq = g + 8 * (q >> 1), jq = tg * 2 + (q & 1);
                sPh[((w * 4 + nf) * 16 + bq) * 8 + jq] =
                    acc1[nf][q] + acc2[nf][q] + acc3[nf][q];
                if (dox)
                    sPx[((w * 4 + nf) * 16 + bq) * 8 + jq] = xa[nf][q] + xb[nf][q];
            }
        __syncthreads();

        // ---- distributed epilogue ----
        float a4[4];
#pragma unroll
        for (int nf = 0; nf < 4; nf++) {
            float s = xp[nf];
#pragma unroll
            for (int ww = 0; ww < 4; ww++)
                s += sPh[((ww * 4 + nf) * 16 + bloc) * 8 + jloc];
            a4[nf] = s;
        }
        float fg = sigm(a4[0]);
        float ig = sigm(a4[1]);
        float og = sigm(a4[2]);
        float Cg = tanh_acc(a4[3]);
        cs = fg * cs + ig * Cg;
        float hout = og * tanh_acc(cs);

        if (dox) {   // xp for next step
#pragma unroll
            for (int nf = 0; nf < 4; nf++) {
                float s = bias_r[nf];
#pragma unroll
                for (int ww = 0; ww < 4; ww++)
                    s += sPx[((ww * 4 + nf) * 16 + bloc) * 8 + jloc];
                xp[nf] = s;
            }
        }

        if (t == T_ - 1) {
            out[(size_t)bglob * H_ + jglob] = hout;
            break;
        }

        // ---- write h_{t+1}: pair via shfl, even lanes store 8B ----
        uint16_t hh, hl;
        bsplit(hout, hh, hl);
        uint32_t mine = bpack(hh, hl);
        uint32_t other = __shfl_xor_sync(0xFFFFFFFF, mine, 1);
        if ((jloc & 1) == 0) {
            uint32_t hiw = (mine & 0xFFFFu) | (other << 16);
            uint32_t low = (mine >> 16) | (other & 0xFFFF0000u);
            __stcg((uint2*)&g_hP[(t + 1) & 1][bglob * 256 + jc * 4 + (jloc >> 1)],
                   make_uint2(hiw, low));
        }
        __syncthreads();                          // h stores ordered before arrive
        if (tid == 0) red_rel(&g_count4[mb]);     // release arrival

        if (tid == 0) {
            while (ld_acq(&g_count4[mb]) < 64 * (t + 1)) {}
        }
        __syncthreads();
    }

    g_cs[(size_t)bglob * H_ + jglob] = cs;
}

// ------------------------- launch ------------------------------------------
extern "C" void kernel_launch(void* const* d_in, const int* in_sizes, int n_in,
                              void* d_out, int out_size) {
    (void)in_sizes; (void)n_in; (void)out_size;
    const float* x  = (const float*)d_in[0];
    const float* Wf = (const float*)d_in[1];
    const float* bf = (const float*)d_in[2];
    const float* Wi = (const float*)d_in[3];
    const float* bi = (const float*)d_in[4];
    const float* Wo = (const float*)d_in[5];
    const float* bo = (const float*)d_in[6];
    const float* Wc = (const float*)d_in[7];
    const float* bc = (const float*)d_in[8];

    cudaFuncSetAttribute(lstm_kernel, cudaFuncAttributeMaxDynamicSharedMemorySize, SMEM2);

    pack_kernel<<<4096, 256>>>(Wf, Wi, Wo, Wc, bf, bi, bo, bc);
    xpack_kernel<<<32768, 256>>>(x);
    for (int s = 0; s < T_ / SEG; s++)
        lstm_kernel<<<NCG, 128, SMEM2>>>((float*)d_out, s * SEG);
}